// round 2
// baseline (speedup 1.0000x reference)
#include <cuda_runtime.h>
#include <math.h>

#define NN 10000
#define EE 160000
#define PP 4000
#define HT_SIZE 16384
#define HT_MASK 16383
#define CAP 128
#define NOTF 0x7fffffff

// ---------------- scratch (device globals; no allocation) ----------------
__device__ float g_xl[NN * 256];
__device__ float g_xr[NN * 256];
__device__ float g_h[NN * 256];
__device__ int g_cnt[NN];
__device__ int g_rowstart[NN + 1];
__device__ int g_cursor[NN];
__device__ int g_eid[EE];
__device__ int g_srcs[EE];
__device__ int g_htk[HT_SIZE];
__device__ int g_htv[HT_SIZE];
__device__ int g_pidx[PP];

// ---------------- setup kernels ----------------
__global__ void init_kernel() {
    int i = blockIdx.x * blockDim.x + threadIdx.x;
    if (i < HT_SIZE) { g_htk[i] = -1; g_htv[i] = NOTF; }
    if (i < NN) g_cnt[i] = 0;
}

__global__ void count_kernel(const int* __restrict__ dst) {
    int e = blockIdx.x * blockDim.x + threadIdx.x;
    if (e < EE) atomicAdd(&g_cnt[dst[e]], 1);
}

__global__ void scan_kernel() {
    __shared__ int part[1024];
    int t = threadIdx.x;
    const int CHUNK = 10;  // 1024*10 >= 10000
    int base = t * CHUNK;
    int loc[CHUNK];
    int s = 0;
    #pragma unroll
    for (int i = 0; i < CHUNK; i++) {
        int idx = base + i;
        int v = (idx < NN) ? g_cnt[idx] : 0;
        loc[i] = s;
        s += v;
    }
    part[t] = s;
    __syncthreads();
    for (int off = 1; off < 1024; off <<= 1) {
        int v = (t >= off) ? part[t - off] : 0;
        __syncthreads();
        part[t] += v;
        __syncthreads();
    }
    int pre = (t > 0) ? part[t - 1] : 0;
    #pragma unroll
    for (int i = 0; i < CHUNK; i++) {
        int idx = base + i;
        if (idx < NN) {
            g_rowstart[idx] = pre + loc[i];
            g_cursor[idx] = pre + loc[i];
        }
    }
    if (t == 1023) g_rowstart[NN] = part[1023];
}

__global__ void scatter_kernel(const int* __restrict__ src, const int* __restrict__ dst) {
    int e = blockIdx.x * blockDim.x + threadIdx.x;
    if (e < EE) {
        int d = dst[e];
        int pos = atomicAdd(&g_cursor[d], 1);
        g_eid[pos] = e;
        g_srcs[pos] = src[e];
    }
}

__device__ __forceinline__ unsigned ht_hash(int key) {
    return ((unsigned)key * 2654435761u) >> 18;  // top 14 bits
}

__global__ void ht_insert_kernel(const int* __restrict__ pe) {
    int tid = blockIdx.x * blockDim.x + threadIdx.x;
    if (tid >= 2 * PP) return;
    int p = tid >> 1;
    int i = pe[p * 2 + 0];
    int j = pe[p * 2 + 1];
    int key = (tid & 1) ? (j * NN + i) : (i * NN + j);
    unsigned slot = ht_hash(key) & HT_MASK;
    while (true) {
        int old = atomicCAS(&g_htk[slot], -1, key);
        if (old == -1 || old == key) break;
        slot = (slot + 1) & HT_MASK;
    }
}

__global__ void ht_scan_kernel(const int* __restrict__ src, const int* __restrict__ dst) {
    int e = blockIdx.x * blockDim.x + threadIdx.x;
    if (e >= EE) return;
    int key = src[e] * NN + dst[e];
    unsigned slot = ht_hash(key) & HT_MASK;
    while (true) {
        int kk = g_htk[slot];
        if (kk == -1) return;
        if (kk == key) { atomicMin(&g_htv[slot], e); return; }
        slot = (slot + 1) & HT_MASK;
    }
}

__device__ __forceinline__ int ht_find(int key) {
    unsigned slot = ht_hash(key) & HT_MASK;
    while (true) {
        int kk = g_htk[slot];
        if (kk == key) return g_htv[slot];
        if (kk == -1) return NOTF;
        slot = (slot + 1) & HT_MASK;
    }
}

__global__ void ht_lookup_kernel(const int* __restrict__ pe) {
    int p = blockIdx.x * blockDim.x + threadIdx.x;
    if (p >= PP) return;
    int i = pe[p * 2 + 0];
    int j = pe[p * 2 + 1];
    int v1 = ht_find(i * NN + j);
    int v2 = ht_find(j * NN + i);
    g_pidx[p] = min(v1, v2);
}

// ---------------- xl/xr dual GEMM: [N,K]@[K,256] + bias, twice ----------------
template <int K>
__global__ __launch_bounds__(256) void gemm_lr(
    const float* __restrict__ X, int use_h,
    const float* __restrict__ Wl, const float* __restrict__ bl,
    const float* __restrict__ Wr, const float* __restrict__ br) {
    __shared__ __align__(16) float xs[K * 16];
    const float* Xp = use_h ? g_h : X;
    int tid = threadIdx.x;
    int nb = blockIdx.x * 16;
    for (int idx = tid; idx < 16 * K; idx += 256) {
        int i = idx / K, k = idx % K;
        xs[k * 16 + i] = Xp[(nb + i) * K + k];
    }
    __syncthreads();
    float accl[16], accr[16];
    #pragma unroll
    for (int i = 0; i < 16; i++) { accl[i] = 0.f; accr[i] = 0.f; }
    for (int k = 0; k < K; k++) {
        float wl = Wl[k * 256 + tid];
        float wr = Wr[k * 256 + tid];
        const float4* xv = reinterpret_cast<const float4*>(xs + k * 16);
        #pragma unroll
        for (int q = 0; q < 4; q++) {
            float4 a = xv[q];
            accl[q * 4 + 0] += a.x * wl; accr[q * 4 + 0] += a.x * wr;
            accl[q * 4 + 1] += a.y * wl; accr[q * 4 + 1] += a.y * wr;
            accl[q * 4 + 2] += a.z * wl; accr[q * 4 + 2] += a.z * wr;
            accl[q * 4 + 3] += a.w * wl; accr[q * 4 + 3] += a.w * wr;
        }
    }
    float bvl = bl[tid], bvr = br[tid];
    #pragma unroll
    for (int i = 0; i < 16; i++) {
        g_xl[(nb + i) * 256 + tid] = accl[i] + bvl;
        g_xr[(nb + i) * 256 + tid] = accr[i] + bvr;
    }
}

// ---------------- GATv2 edge phase: warp per node over CSR ----------------
__device__ __forceinline__ float compute_logit(
    const float* __restrict__ eattr, int sp,
    const float wv[3][8], const float* av, const float* xrv, int ch0) {
    int srcn = g_srcs[sp];
    int eo = g_eid[sp];
    float ea0 = __ldg(eattr + eo * 3 + 0);
    float ea1 = __ldg(eattr + eo * 3 + 1);
    float ea2 = __ldg(eattr + eo * 3 + 2);
    const float4* xp = reinterpret_cast<const float4*>(g_xl + srcn * 256 + ch0);
    float4 xa = xp[0], xb = xp[1];
    float xv[8] = {xa.x, xa.y, xa.z, xa.w, xb.x, xb.y, xb.z, xb.w};
    float part = 0.f;
    #pragma unroll
    for (int k = 0; k < 8; k++) {
        float m = xv[k] + xrv[k] + ea0 * wv[0][k] + ea1 * wv[1][k] + ea2 * wv[2][k];
        m = (m > 0.f) ? m : 0.2f * m;
        part += m * av[k];
    }
    part += __shfl_xor_sync(0xffffffffu, part, 1);
    part += __shfl_xor_sync(0xffffffffu, part, 2);
    part += __shfl_xor_sync(0xffffffffu, part, 4);
    return part;
}

__global__ __launch_bounds__(256) void gat_edge(
    const float* __restrict__ eattr, const float* __restrict__ We,
    const float* __restrict__ att, const float* __restrict__ bias) {
    __shared__ float slog[8][CAP * 4];
    int tid = threadIdx.x;
    int l = tid & 31;
    int wib = tid >> 5;
    int node = blockIdx.x * 8 + wib;
    int ch0 = l * 8;
    int head = l >> 3;

    float wv[3][8];
    #pragma unroll
    for (int d = 0; d < 3; d++)
        #pragma unroll
        for (int k = 0; k < 8; k++) wv[d][k] = We[d * 256 + ch0 + k];
    float av[8];
    #pragma unroll
    for (int k = 0; k < 8; k++) av[k] = att[head * 64 + ((ch0 + k) & 63)];
    float xrv[8];
    {
        const float4* rp = reinterpret_cast<const float4*>(g_xr + node * 256 + ch0);
        float4 ra = rp[0], rb = rp[1];
        xrv[0] = ra.x; xrv[1] = ra.y; xrv[2] = ra.z; xrv[3] = ra.w;
        xrv[4] = rb.x; xrv[5] = rb.y; xrv[6] = rb.z; xrv[7] = rb.w;
    }
    int s = g_rowstart[node];
    int en = g_rowstart[node + 1];
    int deg = en - s;

    float runmax = -1e30f;
    for (int kk = 0; kk < deg; kk++) {
        float lg = compute_logit(eattr, s + kk, wv, av, xrv, ch0);
        runmax = fmaxf(runmax, lg);
        if ((l & 7) == 0 && kk < CAP) slog[wib][kk * 4 + head] = lg;
    }
    __syncwarp();
    float sumex = 0.f;
    for (int kk = 0; kk < deg; kk++) {
        float lg = (kk < CAP) ? slog[wib][kk * 4 + head]
                              : compute_logit(eattr, s + kk, wv, av, xrv, ch0);
        sumex += __expf(lg - runmax);
    }
    float den = sumex + 1e-16f;

    float acc[8];
    #pragma unroll
    for (int k = 0; k < 8; k++) acc[k] = 0.f;
    for (int kk = 0; kk < deg; kk++) {
        float lg = (kk < CAP) ? slog[wib][kk * 4 + head]
                              : compute_logit(eattr, s + kk, wv, av, xrv, ch0);
        float alpha = __expf(lg - runmax) / den;
        int srcn = g_srcs[s + kk];
        const float4* xp = reinterpret_cast<const float4*>(g_xl + srcn * 256 + ch0);
        float4 xa = xp[0], xb = xp[1];
        acc[0] += alpha * xa.x; acc[1] += alpha * xa.y;
        acc[2] += alpha * xa.z; acc[3] += alpha * xa.w;
        acc[4] += alpha * xb.x; acc[5] += alpha * xb.y;
        acc[6] += alpha * xb.z; acc[7] += alpha * xb.w;
    }
    float o[8];
    #pragma unroll
    for (int k = 0; k < 8; k++) {
        float v = acc[k] + bias[ch0 + k];
        o[k] = (v > 0.f) ? v : expm1f(v);
    }
    float4* hp = reinterpret_cast<float4*>(g_h + node * 256 + ch0);
    hp[0] = make_float4(o[0], o[1], o[2], o[3]);
    hp[1] = make_float4(o[4], o[5], o[6], o[7]);
}

// ---------------- edge-quality head: 515 -> 64 -> 32 -> 1 ----------------
__global__ __launch_bounds__(256) void edge_head(
    const int* __restrict__ pe, const float* __restrict__ eattr,
    const float* __restrict__ Wq1, const float* __restrict__ bq1,
    const float* __restrict__ Wq2, const float* __restrict__ bq2,
    const float* __restrict__ Wq3, const float* __restrict__ bq3,
    float* __restrict__ out) {
    __shared__ float efs[8][520];
    __shared__ float eq1[8][64];
    __shared__ float eq2[8][33];
    int tid = threadIdx.x;
    int pb = blockIdx.x * 8;
    for (int e8 = 0; e8 < 8; e8++) {
        int p = pb + e8;
        int i = pe[p * 2 + 0];
        int j = pe[p * 2 + 1];
        int idx = g_pidx[p];
        for (int t = tid; t < 515; t += 256) {
            float v;
            if (t < 256) v = g_h[i * 256 + t];
            else if (t < 512) v = g_h[j * 256 + (t - 256)];
            else v = (idx < NOTF) ? eattr[idx * 3 + (t - 512)] : 0.f;
            efs[e8][t] = v;
        }
    }
    __syncthreads();
    // stage 1
    {
        int oc = tid & 63;
        int grp = tid >> 6;
        float a0 = 0.f, a1 = 0.f;
        const float* ef0 = efs[grp * 2 + 0];
        const float* ef1 = efs[grp * 2 + 1];
        for (int k = 0; k < 515; k++) {
            float w = Wq1[k * 64 + oc];
            a0 += ef0[k] * w;
            a1 += ef1[k] * w;
        }
        float bb = bq1[oc];
        a0 += bb; a1 += bb;
        a0 = (a0 > 0.f) ? a0 : expm1f(a0);
        a1 = (a1 > 0.f) ? a1 : expm1f(a1);
        eq1[grp * 2 + 0][oc] = a0;
        eq1[grp * 2 + 1][oc] = a1;
    }
    __syncthreads();
    // stage 2
    {
        int oc2 = tid & 31;
        int e8 = tid >> 5;
        float a = 0.f;
        for (int k = 0; k < 64; k++) a += eq1[e8][k] * Wq2[k * 32 + oc2];
        a += bq2[oc2];
        a = (a > 0.f) ? a : expm1f(a);
        eq2[e8][oc2] = a;
    }
    __syncthreads();
    // stage 3
    {
        int w8 = tid >> 5;
        int lane = tid & 31;
        float v = eq2[w8][lane] * Wq3[lane];
        v += __shfl_xor_sync(0xffffffffu, v, 16);
        v += __shfl_xor_sync(0xffffffffu, v, 8);
        v += __shfl_xor_sync(0xffffffffu, v, 4);
        v += __shfl_xor_sync(0xffffffffu, v, 2);
        v += __shfl_xor_sync(0xffffffffu, v, 1);
        if (lane == 0) out[pb + w8] = v + bq3[0];
    }
}

// ---------------- node swap head: 256 -> 64 -> 32 -> 1 ----------------
__global__ __launch_bounds__(256) void node_head(
    const float* __restrict__ Wn1, const float* __restrict__ bn1,
    const float* __restrict__ Wn2, const float* __restrict__ bn2,
    const float* __restrict__ Wn3, const float* __restrict__ bn3,
    float* __restrict__ out) {
    __shared__ float hs[16][256];
    __shared__ float eq1[16][64];
    __shared__ float eq2[16][33];
    int tid = threadIdx.x;
    int nb = blockIdx.x * 16;
    for (int t = tid; t < 16 * 256; t += 256) {
        int i = t >> 8;
        int c = t & 255;
        hs[i][c] = g_h[(nb + i) * 256 + c];
    }
    __syncthreads();
    // stage 1
    {
        int oc = tid & 63;
        int grp = tid >> 6;  // 0..3, each 4 nodes
        float acc[4] = {0.f, 0.f, 0.f, 0.f};
        for (int k = 0; k < 256; k++) {
            float w = Wn1[k * 64 + oc];
            #pragma unroll
            for (int q = 0; q < 4; q++) acc[q] += hs[grp * 4 + q][k] * w;
        }
        float bb = bn1[oc];
        #pragma unroll
        for (int q = 0; q < 4; q++) {
            float a = acc[q] + bb;
            a = (a > 0.f) ? a : expm1f(a);
            eq1[grp * 4 + q][oc] = a;
        }
    }
    __syncthreads();
    // stage 2
    {
        int oc2 = tid & 31;
        int g2 = tid >> 5;  // 0..7, each 2 nodes
        float b0 = 0.f, b1 = 0.f;
        for (int k = 0; k < 64; k++) {
            float w = Wn2[k * 32 + oc2];
            b0 += eq1[g2 * 2 + 0][k] * w;
            b1 += eq1[g2 * 2 + 1][k] * w;
        }
        float bb2 = bn2[oc2];
        b0 += bb2; b1 += bb2;
        b0 = (b0 > 0.f) ? b0 : expm1f(b0);
        b1 = (b1 > 0.f) ? b1 : expm1f(b1);
        eq2[g2 * 2 + 0][oc2] = b0;
        eq2[g2 * 2 + 1][oc2] = b1;
    }
    __syncthreads();
    // stage 3
    {
        int w8 = tid >> 5;
        int lane = tid & 31;
        #pragma unroll
        for (int q = 0; q < 2; q++) {
            int nl = w8 * 2 + q;
            float v = eq2[nl][lane] * Wn3[lane];
            v += __shfl_xor_sync(0xffffffffu, v, 16);
            v += __shfl_xor_sync(0xffffffffu, v, 8);
            v += __shfl_xor_sync(0xffffffffu, v, 4);
            v += __shfl_xor_sync(0xffffffffu, v, 2);
            v += __shfl_xor_sync(0xffffffffu, v, 1);
            if (lane == 0) out[nb + nl] = v + bn3[0];
        }
    }
}

// ---------------- launch ----------------
extern "C" void kernel_launch(void* const* d_in, const int* in_sizes, int n_in,
                              void* d_out, int out_size) {
    const float* x   = (const float*)d_in[0];
    const int*   ei  = (const int*)d_in[1];
    const float* ea  = (const float*)d_in[2];
    const int*   pe  = (const int*)d_in[3];
    const float* Wl1 = (const float*)d_in[4];
    const float* bl1 = (const float*)d_in[5];
    const float* Wr1 = (const float*)d_in[6];
    const float* br1 = (const float*)d_in[7];
    const float* We1 = (const float*)d_in[8];
    const float* att1= (const float*)d_in[9];
    const float* b1  = (const float*)d_in[10];
    const float* Wl2 = (const float*)d_in[11];
    const float* bl2 = (const float*)d_in[12];
    const float* Wr2 = (const float*)d_in[13];
    const float* br2 = (const float*)d_in[14];
    const float* We2 = (const float*)d_in[15];
    const float* att2= (const float*)d_in[16];
    const float* b2  = (const float*)d_in[17];
    const float* Wq1 = (const float*)d_in[18];
    const float* bq1 = (const float*)d_in[19];
    const float* Wq2 = (const float*)d_in[20];
    const float* bq2 = (const float*)d_in[21];
    const float* Wq3 = (const float*)d_in[22];
    const float* bq3 = (const float*)d_in[23];
    const float* Wn1 = (const float*)d_in[24];
    const float* bn1 = (const float*)d_in[25];
    const float* Wn2 = (const float*)d_in[26];
    const float* bn2 = (const float*)d_in[27];
    const float* Wn3 = (const float*)d_in[28];
    const float* bn3 = (const float*)d_in[29];
    float* out = (float*)d_out;

    const int* src = ei;
    const int* dst = ei + EE;

    // setup: CSR by dst + physical-edge min-index hash
    init_kernel<<<(HT_SIZE + 255) / 256, 256>>>();
    count_kernel<<<(EE + 255) / 256, 256>>>(dst);
    scan_kernel<<<1, 1024>>>();
    scatter_kernel<<<(EE + 255) / 256, 256>>>(src, dst);
    ht_insert_kernel<<<(2 * PP + 255) / 256, 256>>>(pe);
    ht_scan_kernel<<<(EE + 255) / 256, 256>>>(src, dst);
    ht_lookup_kernel<<<(PP + 255) / 256, 256>>>(pe);

    // layer 1
    gemm_lr<8><<<NN / 16, 256>>>(x, 0, Wl1, bl1, Wr1, br1);
    gat_edge<<<NN / 8, 256>>>(ea, We1, att1, b1);
    // layer 2
    gemm_lr<256><<<NN / 16, 256>>>(nullptr, 1, Wl2, bl2, Wr2, br2);
    gat_edge<<<NN / 8, 256>>>(ea, We2, att2, b2);

    // heads
    edge_head<<<PP / 8, 256>>>(pe, ea, Wq1, bq1, Wq2, bq2, Wq3, bq3, out);
    node_head<<<NN / 16, 256>>>(Wn1, bn1, Wn2, bn2, Wn3, bn3, out + PP);
}

// round 3
// speedup vs baseline: 1.2051x; 1.2051x over previous
#include <cuda_runtime.h>
#include <math.h>

#define NN 10000
#define EE 160000
#define PP 4000
#define HT_SIZE 16384
#define HT_MASK 16383
#define NOTF 0x7fffffff

typedef unsigned long long ull;

// ---------------- f32x2 packed helpers (Blackwell) ----------------
__device__ __forceinline__ ull pack2(float lo, float hi) {
    ull r; asm("mov.b64 %0,{%1,%2};" : "=l"(r) : "f"(lo), "f"(hi)); return r;
}
__device__ __forceinline__ float2 unpack2(ull v) {
    float2 r; asm("mov.b64 {%0,%1},%2;" : "=f"(r.x), "=f"(r.y) : "l"(v)); return r;
}
__device__ __forceinline__ ull fma2(ull a, ull b, ull c) {
    ull d; asm("fma.rn.f32x2 %0,%1,%2,%3;" : "=l"(d) : "l"(a), "l"(b), "l"(c)); return d;
}
__device__ __forceinline__ ull mul2(ull a, ull b) {
    ull d; asm("mul.rn.f32x2 %0,%1,%2;" : "=l"(d) : "l"(a), "l"(b)); return d;
}

// ---------------- scratch (device globals; no allocation) ----------------
__device__ float g_xl[NN * 256];
__device__ float g_xr[NN * 256];
__device__ float g_h[NN * 256];
__device__ int g_cnt[NN];
__device__ int g_rowstart[NN + 1];
__device__ int g_cursor[NN];
__device__ int2 g_es[EE];   // .x = src node, .y = original edge id
__device__ int g_htk[HT_SIZE];
__device__ int g_htv[HT_SIZE];
__device__ int g_pidx[PP];

// ---------------- fused setup kernels ----------------
__global__ void initA_kernel() {
    int i = blockIdx.x * blockDim.x + threadIdx.x;
    if (i < HT_SIZE) { g_htk[i] = -1; g_htv[i] = NOTF; }
    if (i < NN) g_cnt[i] = 0;
}

__device__ __forceinline__ unsigned ht_hash(int key) {
    return ((unsigned)key * 2654435761u) >> 18;
}

// count degrees (E threads) + hash-insert physical keys (2P threads)
__global__ void count_insert_kernel(const int* __restrict__ dst, const int* __restrict__ pe) {
    int e = blockIdx.x * blockDim.x + threadIdx.x;
    if (e < EE) atomicAdd(&g_cnt[dst[e]], 1);
    if (e < 2 * PP) {
        int p = e >> 1;
        int i = pe[p * 2 + 0];
        int j = pe[p * 2 + 1];
        int key = (e & 1) ? (j * NN + i) : (i * NN + j);
        unsigned slot = ht_hash(key) & HT_MASK;
        while (true) {
            int old = atomicCAS(&g_htk[slot], -1, key);
            if (old == -1 || old == key) break;
            slot = (slot + 1) & HT_MASK;
        }
    }
}

__global__ void scan_kernel() {
    __shared__ int part[1024];
    int t = threadIdx.x;
    const int CHUNK = 10;
    int base = t * CHUNK;
    int loc[CHUNK];
    int s = 0;
    #pragma unroll
    for (int i = 0; i < CHUNK; i++) {
        int idx = base + i;
        int v = (idx < NN) ? g_cnt[idx] : 0;
        loc[i] = s;
        s += v;
    }
    part[t] = s;
    __syncthreads();
    for (int off = 1; off < 1024; off <<= 1) {
        int v = (t >= off) ? part[t - off] : 0;
        __syncthreads();
        part[t] += v;
        __syncthreads();
    }
    int pre = (t > 0) ? part[t - 1] : 0;
    #pragma unroll
    for (int i = 0; i < CHUNK; i++) {
        int idx = base + i;
        if (idx < NN) {
            g_rowstart[idx] = pre + loc[i];
            g_cursor[idx] = pre + loc[i];
        }
    }
    if (t == 1023) g_rowstart[NN] = part[1023];
}

// scatter into CSR + hash-scan for min original edge index, fused over E
__global__ void scatter_scan_kernel(const int* __restrict__ src, const int* __restrict__ dst) {
    int e = blockIdx.x * blockDim.x + threadIdx.x;
    if (e >= EE) return;
    int sN = src[e], dN = dst[e];
    int pos = atomicAdd(&g_cursor[dN], 1);
    g_es[pos] = make_int2(sN, e);
    int key = sN * NN + dN;
    unsigned slot = ht_hash(key) & HT_MASK;
    while (true) {
        int kk = g_htk[slot];
        if (kk == -1) return;
        if (kk == key) { atomicMin(&g_htv[slot], e); return; }
        slot = (slot + 1) & HT_MASK;
    }
}

__device__ __forceinline__ int ht_find(int key) {
    unsigned slot = ht_hash(key) & HT_MASK;
    while (true) {
        int kk = g_htk[slot];
        if (kk == key) return g_htv[slot];
        if (kk == -1) return NOTF;
        slot = (slot + 1) & HT_MASK;
    }
}

__global__ void ht_lookup_kernel(const int* __restrict__ pe) {
    int p = blockIdx.x * blockDim.x + threadIdx.x;
    if (p >= PP) return;
    int i = pe[p * 2 + 0];
    int j = pe[p * 2 + 1];
    int v1 = ht_find(i * NN + j);
    int v2 = ht_find(j * NN + i);
    g_pidx[p] = min(v1, v2);
}

// ---------------- xl/xr dual GEMM with packed f32x2 FMA ----------------
template <int K>
__global__ __launch_bounds__(256) void gemm_lr(
    const float* __restrict__ X, int use_h,
    const float* __restrict__ Wl, const float* __restrict__ bl,
    const float* __restrict__ Wr, const float* __restrict__ br) {
    __shared__ __align__(16) float xs[K * 16];
    const float* Xp = use_h ? g_h : X;
    int tid = threadIdx.x;
    int nb = blockIdx.x * 16;
    for (int idx = tid; idx < 16 * K; idx += 256) {
        int i = idx / K, k = idx % K;
        xs[k * 16 + i] = Xp[(nb + i) * K + k];
    }
    __syncthreads();
    ull accl[8], accr[8];
    #pragma unroll
    for (int q = 0; q < 8; q++) { accl[q] = 0ULL; accr[q] = 0ULL; }
    for (int k = 0; k < K; k++) {
        float wl = __ldg(Wl + k * 256 + tid);
        float wr = __ldg(Wr + k * 256 + tid);
        ull wl2 = pack2(wl, wl);
        ull wr2 = pack2(wr, wr);
        const ulonglong2* xv = reinterpret_cast<const ulonglong2*>(xs + k * 16);
        #pragma unroll
        for (int q2 = 0; q2 < 4; q2++) {
            ulonglong2 a = xv[q2];
            accl[q2 * 2 + 0] = fma2(a.x, wl2, accl[q2 * 2 + 0]);
            accl[q2 * 2 + 1] = fma2(a.y, wl2, accl[q2 * 2 + 1]);
            accr[q2 * 2 + 0] = fma2(a.x, wr2, accr[q2 * 2 + 0]);
            accr[q2 * 2 + 1] = fma2(a.y, wr2, accr[q2 * 2 + 1]);
        }
    }
    float bvl = bl[tid], bvr = br[tid];
    #pragma unroll
    for (int q = 0; q < 8; q++) {
        float2 vl = unpack2(accl[q]);
        float2 vr = unpack2(accr[q]);
        g_xl[(nb + 2 * q + 0) * 256 + tid] = vl.x + bvl;
        g_xl[(nb + 2 * q + 1) * 256 + tid] = vl.y + bvl;
        g_xr[(nb + 2 * q + 0) * 256 + tid] = vr.x + bvr;
        g_xr[(nb + 2 * q + 1) * 256 + tid] = vr.y + bvr;
    }
}

// ---------------- GATv2 edge phase: single-pass online softmax ----------------
__global__ __launch_bounds__(256) void gat_edge(
    const float* __restrict__ eattr, const float* __restrict__ We,
    const float* __restrict__ att, const float* __restrict__ bias) {
    int tid = threadIdx.x;
    int l = tid & 31;
    int wib = tid >> 5;
    int node = blockIdx.x * 8 + wib;
    int ch0 = l * 8;
    int head = l >> 3;

    float wv0[8], wv1[8], wv2[8], av[8], xrv[8];
    #pragma unroll
    for (int k = 0; k < 8; k++) {
        wv0[k] = We[0 * 256 + ch0 + k];
        wv1[k] = We[1 * 256 + ch0 + k];
        wv2[k] = We[2 * 256 + ch0 + k];
        av[k] = att[head * 64 + ((ch0 + k) & 63)];
    }
    {
        const float4* rp = reinterpret_cast<const float4*>(g_xr + node * 256 + ch0);
        float4 ra = rp[0], rb = rp[1];
        xrv[0] = ra.x; xrv[1] = ra.y; xrv[2] = ra.z; xrv[3] = ra.w;
        xrv[4] = rb.x; xrv[5] = rb.y; xrv[6] = rb.z; xrv[7] = rb.w;
    }
    int s0 = g_rowstart[node];
    int en = g_rowstart[node + 1];

    float m = -1e30f, ssum = 0.f;
    ull acc2[4] = {0ULL, 0ULL, 0ULL, 0ULL};

    for (int sp = s0; sp < en; sp++) {
        int2 es = g_es[sp];
        float ea0 = __ldg(eattr + es.y * 3 + 0);
        float ea1 = __ldg(eattr + es.y * 3 + 1);
        float ea2 = __ldg(eattr + es.y * 3 + 2);
        const float4* xp = reinterpret_cast<const float4*>(g_xl + es.x * 256 + ch0);
        float4 xa = xp[0], xb = xp[1];
        float xv[8] = {xa.x, xa.y, xa.z, xa.w, xb.x, xb.y, xb.z, xb.w};
        float part = 0.f;
        #pragma unroll
        for (int k = 0; k < 8; k++) {
            float t = xv[k] + xrv[k];
            t = fmaf(ea0, wv0[k], t);
            t = fmaf(ea1, wv1[k], t);
            t = fmaf(ea2, wv2[k], t);
            t = fmaxf(t, 0.2f * t);       // leaky_relu(t, 0.2)
            part = fmaf(t, av[k], part);
        }
        part += __shfl_xor_sync(0xffffffffu, part, 1);
        part += __shfl_xor_sync(0xffffffffu, part, 2);
        part += __shfl_xor_sync(0xffffffffu, part, 4);

        float mn = fmaxf(m, part);
        float sc = __expf(m - mn);        // rescale of running state (1 if no new max)
        float p = __expf(part - mn);
        ssum = fmaf(ssum, sc, p);
        ull sc2 = pack2(sc, sc);
        ull p2 = pack2(p, p);
        acc2[0] = fma2(acc2[0], sc2, mul2(p2, pack2(xv[0], xv[1])));
        acc2[1] = fma2(acc2[1], sc2, mul2(p2, pack2(xv[2], xv[3])));
        acc2[2] = fma2(acc2[2], sc2, mul2(p2, pack2(xv[4], xv[5])));
        acc2[3] = fma2(acc2[3], sc2, mul2(p2, pack2(xv[6], xv[7])));
        m = mn;
    }

    float inv = 1.f / (ssum + 1e-16f);
    float o[8];
    #pragma unroll
    for (int q = 0; q < 4; q++) {
        float2 a = unpack2(acc2[q]);
        float v0 = a.x * inv + bias[ch0 + 2 * q + 0];
        float v1 = a.y * inv + bias[ch0 + 2 * q + 1];
        o[2 * q + 0] = (v0 > 0.f) ? v0 : expm1f(v0);
        o[2 * q + 1] = (v1 > 0.f) ? v1 : expm1f(v1);
    }
    float4* hp = reinterpret_cast<float4*>(g_h + node * 256 + ch0);
    hp[0] = make_float4(o[0], o[1], o[2], o[3]);
    hp[1] = make_float4(o[4], o[5], o[6], o[7]);
}

// ---------------- edge-quality head: 515 -> 64 -> 32 -> 1 ----------------
__global__ __launch_bounds__(256) void edge_head(
    const int* __restrict__ pe, const float* __restrict__ eattr,
    const float* __restrict__ Wq1, const float* __restrict__ bq1,
    const float* __restrict__ Wq2, const float* __restrict__ bq2,
    const float* __restrict__ Wq3, const float* __restrict__ bq3,
    float* __restrict__ out) {
    __shared__ float efs[8][520];
    __shared__ float eq1[8][64];
    __shared__ float eq2[8][33];
    int tid = threadIdx.x;
    int pb = blockIdx.x * 8;
    for (int e8 = 0; e8 < 8; e8++) {
        int p = pb + e8;
        int i = pe[p * 2 + 0];
        int j = pe[p * 2 + 1];
        int idx = g_pidx[p];
        for (int t = tid; t < 515; t += 256) {
            float v;
            if (t < 256) v = g_h[i * 256 + t];
            else if (t < 512) v = g_h[j * 256 + (t - 256)];
            else v = (idx < NOTF) ? eattr[idx * 3 + (t - 512)] : 0.f;
            efs[e8][t] = v;
        }
    }
    __syncthreads();
    {
        int oc = tid & 63;
        int grp = tid >> 6;
        ull a01 = 0ULL;
        const float* ef0 = efs[grp * 2 + 0];
        const float* ef1 = efs[grp * 2 + 1];
        for (int k = 0; k < 515; k++) {
            float w = __ldg(Wq1 + k * 64 + oc);
            a01 = fma2(pack2(ef0[k], ef1[k]), pack2(w, w), a01);
        }
        float bb = bq1[oc];
        float2 a = unpack2(a01);
        float a0 = a.x + bb, a1 = a.y + bb;
        a0 = (a0 > 0.f) ? a0 : expm1f(a0);
        a1 = (a1 > 0.f) ? a1 : expm1f(a1);
        eq1[grp * 2 + 0][oc] = a0;
        eq1[grp * 2 + 1][oc] = a1;
    }
    __syncthreads();
    {
        int oc2 = tid & 31;
        int e8 = tid >> 5;
        float a = 0.f;
        for (int k = 0; k < 64; k++) a = fmaf(eq1[e8][k], Wq2[k * 32 + oc2], a);
        a += bq2[oc2];
        a = (a > 0.f) ? a : expm1f(a);
        eq2[e8][oc2] = a;
    }
    __syncthreads();
    {
        int w8 = tid >> 5;
        int lane = tid & 31;
        float v = eq2[w8][lane] * Wq3[lane];
        v += __shfl_xor_sync(0xffffffffu, v, 16);
        v += __shfl_xor_sync(0xffffffffu, v, 8);
        v += __shfl_xor_sync(0xffffffffu, v, 4);
        v += __shfl_xor_sync(0xffffffffu, v, 2);
        v += __shfl_xor_sync(0xffffffffu, v, 1);
        if (lane == 0) out[pb + w8] = v + bq3[0];
    }
}

// ---------------- node swap head: 256 -> 64 -> 32 -> 1 ----------------
__global__ __launch_bounds__(256) void node_head(
    const float* __restrict__ Wn1, const float* __restrict__ bn1,
    const float* __restrict__ Wn2, const float* __restrict__ bn2,
    const float* __restrict__ Wn3, const float* __restrict__ bn3,
    float* __restrict__ out) {
    __shared__ float hs[16][256];
    __shared__ float eq1[16][64];
    __shared__ float eq2[16][33];
    int tid = threadIdx.x;
    int nb = blockIdx.x * 16;
    for (int t = tid; t < 16 * 256; t += 256) {
        int i = t >> 8;
        int c = t & 255;
        hs[i][c] = g_h[(nb + i) * 256 + c];
    }
    __syncthreads();
    {
        int oc = tid & 63;
        int grp = tid >> 6;
        ull acc01 = 0ULL, acc23 = 0ULL;
        for (int k = 0; k < 256; k++) {
            float w = __ldg(Wn1 + k * 64 + oc);
            ull w2 = pack2(w, w);
            acc01 = fma2(pack2(hs[grp * 4 + 0][k], hs[grp * 4 + 1][k]), w2, acc01);
            acc23 = fma2(pack2(hs[grp * 4 + 2][k], hs[grp * 4 + 3][k]), w2, acc23);
        }
        float bb = bn1[oc];
        float2 a01 = unpack2(acc01);
        float2 a23 = unpack2(acc23);
        float v[4] = {a01.x + bb, a01.y + bb, a23.x + bb, a23.y + bb};
        #pragma unroll
        for (int q = 0; q < 4; q++) {
            float a = v[q];
            a = (a > 0.f) ? a : expm1f(a);
            eq1[grp * 4 + q][oc] = a;
        }
    }
    __syncthreads();
    {
        int oc2 = tid & 31;
        int g2 = tid >> 5;
        ull b01 = 0ULL;
        for (int k = 0; k < 64; k++) {
            float w = Wn2[k * 32 + oc2];
            b01 = fma2(pack2(eq1[g2 * 2 + 0][k], eq1[g2 * 2 + 1][k]), pack2(w, w), b01);
        }
        float bb2 = bn2[oc2];
        float2 b = unpack2(b01);
        float b0 = b.x + bb2, b1 = b.y + bb2;
        b0 = (b0 > 0.f) ? b0 : expm1f(b0);
        b1 = (b1 > 0.f) ? b1 : expm1f(b1);
        eq2[g2 * 2 + 0][oc2] = b0;
        eq2[g2 * 2 + 1][oc2] = b1;
    }
    __syncthreads();
    {
        int w8 = tid >> 5;
        int lane = tid & 31;
        #pragma unroll
        for (int q = 0; q < 2; q++) {
            int nl = w8 * 2 + q;
            float v = eq2[nl][lane] * Wn3[lane];
            v += __shfl_xor_sync(0xffffffffu, v, 16);
            v += __shfl_xor_sync(0xffffffffu, v, 8);
            v += __shfl_xor_sync(0xffffffffu, v, 4);
            v += __shfl_xor_sync(0xffffffffu, v, 2);
            v += __shfl_xor_sync(0xffffffffu, v, 1);
            if (lane == 0) out[nb + nl] = v + bn3[0];
        }
    }
}

// ---------------- launch ----------------
extern "C" void kernel_launch(void* const* d_in, const int* in_sizes, int n_in,
                              void* d_out, int out_size) {
    const float* x   = (const float*)d_in[0];
    const int*   ei  = (const int*)d_in[1];
    const float* ea  = (const float*)d_in[2];
    const int*   pe  = (const int*)d_in[3];
    const float* Wl1 = (const float*)d_in[4];
    const float* bl1 = (const float*)d_in[5];
    const float* Wr1 = (const float*)d_in[6];
    const float* br1 = (const float*)d_in[7];
    const float* We1 = (const float*)d_in[8];
    const float* att1= (const float*)d_in[9];
    const float* b1  = (const float*)d_in[10];
    const float* Wl2 = (const float*)d_in[11];
    const float* bl2 = (const float*)d_in[12];
    const float* Wr2 = (const float*)d_in[13];
    const float* br2 = (const float*)d_in[14];
    const float* We2 = (const float*)d_in[15];
    const float* att2= (const float*)d_in[16];
    const float* b2  = (const float*)d_in[17];
    const float* Wq1 = (const float*)d_in[18];
    const float* bq1 = (const float*)d_in[19];
    const float* Wq2 = (const float*)d_in[20];
    const float* bq2 = (const float*)d_in[21];
    const float* Wq3 = (const float*)d_in[22];
    const float* bq3 = (const float*)d_in[23];
    const float* Wn1 = (const float*)d_in[24];
    const float* bn1 = (const float*)d_in[25];
    const float* Wn2 = (const float*)d_in[26];
    const float* bn2 = (const float*)d_in[27];
    const float* Wn3 = (const float*)d_in[28];
    const float* bn3 = (const float*)d_in[29];
    float* out = (float*)d_out;

    const int* src = ei;
    const int* dst = ei + EE;

    // setup: CSR by dst + physical-edge min-index hash (fused)
    initA_kernel<<<(HT_SIZE + 255) / 256, 256>>>();
    count_insert_kernel<<<(EE + 255) / 256, 256>>>(dst, pe);
    scan_kernel<<<1, 1024>>>();
    scatter_scan_kernel<<<(EE + 255) / 256, 256>>>(src, dst);
    ht_lookup_kernel<<<(PP + 255) / 256, 256>>>(pe);

    // layer 1
    gemm_lr<8><<<NN / 16, 256>>>(x, 0, Wl1, bl1, Wr1, br1);
    gat_edge<<<NN / 8, 256>>>(ea, We1, att1, b1);
    // layer 2
    gemm_lr<256><<<NN / 16, 256>>>(nullptr, 1, Wl2, bl2, Wr2, br2);
    gat_edge<<<NN / 8, 256>>>(ea, We2, att2, b2);

    // heads
    edge_head<<<PP / 8, 256>>>(pe, ea, Wq1, bq1, Wq2, bq2, Wq3, bq3, out);
    node_head<<<NN / 16, 256>>>(Wn1, bn1, Wn2, bn2, Wn3, bn3, out + PP);
}

// round 4
// speedup vs baseline: 1.3168x; 1.0927x over previous
#include <cuda_runtime.h>
#include <math.h>

#define NN 10000
#define EE 160000
#define PP 4000
#define HT_SIZE 16384
#define HT_MASK 16383
#define NOTF 0x7fffffff

typedef unsigned long long ull;

// ---------------- f32x2 packed helpers (Blackwell) ----------------
__device__ __forceinline__ ull pack2(float lo, float hi) {
    ull r; asm("mov.b64 %0,{%1,%2};" : "=l"(r) : "f"(lo), "f"(hi)); return r;
}
__device__ __forceinline__ float2 unpack2(ull v) {
    float2 r; asm("mov.b64 {%0,%1},%2;" : "=f"(r.x), "=f"(r.y) : "l"(v)); return r;
}
__device__ __forceinline__ ull fma2(ull a, ull b, ull c) {
    ull d; asm("fma.rn.f32x2 %0,%1,%2,%3;" : "=l"(d) : "l"(a), "l"(b), "l"(c)); return d;
}
__device__ __forceinline__ ull mul2(ull a, ull b) {
    ull d; asm("mul.rn.f32x2 %0,%1,%2;" : "=l"(d) : "l"(a), "l"(b)); return d;
}

// ---------------- scratch (device globals; no allocation) ----------------
__device__ float g_xl[NN * 256];
__device__ float g_xr[NN * 256];
__device__ float g_h[NN * 256];
__device__ int g_cnt[NN];
__device__ int g_rowstart[NN + 1];
__device__ int g_cursor[NN];
__device__ int2 g_es[EE];   // .x = src node, .y = original edge id
__device__ int g_htk[HT_SIZE];
__device__ int g_htv[HT_SIZE];

__device__ __forceinline__ unsigned ht_hash(int key) {
    return ((unsigned)key * 2654435761u) >> 18;
}
__device__ __forceinline__ int ht_find(int key) {
    unsigned slot = ht_hash(key) & HT_MASK;
    while (true) {
        int kk = g_htk[slot];
        if (kk == key) return g_htv[slot];
        if (kk == -1) return NOTF;
        slot = (slot + 1) & HT_MASK;
    }
}

// ---------------- K1: init hash/counts (blocks 0..63) + layer-1 GEMM (blocks 64..688) ----------------
__global__ __launch_bounds__(256) void k_init_gemm1(
    const float* __restrict__ X,
    const float* __restrict__ Wl, const float* __restrict__ bl,
    const float* __restrict__ Wr, const float* __restrict__ br) {
    if (blockIdx.x < 64) {
        int i = blockIdx.x * 256 + threadIdx.x;
        if (i < HT_SIZE) { g_htk[i] = -1; g_htv[i] = NOTF; }
        if (i < NN) g_cnt[i] = 0;
        return;
    }
    // layer-1 dual GEMM: [16,8] @ [8,256], per block
    __shared__ __align__(16) float xs[8 * 16];
    int tid = threadIdx.x;
    int nb = (blockIdx.x - 64) * 16;
    if (tid < 128) {
        int i = tid / 8, k = tid % 8;
        xs[k * 16 + i] = X[(nb + i) * 8 + k];
    }
    __syncthreads();
    ull accl[8], accr[8];
    #pragma unroll
    for (int q = 0; q < 8; q++) { accl[q] = 0ULL; accr[q] = 0ULL; }
    #pragma unroll
    for (int k = 0; k < 8; k++) {
        float wl = __ldg(Wl + k * 256 + tid);
        float wr = __ldg(Wr + k * 256 + tid);
        ull wl2 = pack2(wl, wl);
        ull wr2 = pack2(wr, wr);
        const ulonglong2* xv = reinterpret_cast<const ulonglong2*>(xs + k * 16);
        #pragma unroll
        for (int q2 = 0; q2 < 4; q2++) {
            ulonglong2 a = xv[q2];
            accl[q2 * 2 + 0] = fma2(a.x, wl2, accl[q2 * 2 + 0]);
            accl[q2 * 2 + 1] = fma2(a.y, wl2, accl[q2 * 2 + 1]);
            accr[q2 * 2 + 0] = fma2(a.x, wr2, accr[q2 * 2 + 0]);
            accr[q2 * 2 + 1] = fma2(a.y, wr2, accr[q2 * 2 + 1]);
        }
    }
    float bvl = bl[tid], bvr = br[tid];
    #pragma unroll
    for (int q = 0; q < 8; q++) {
        float2 vl = unpack2(accl[q]);
        float2 vr = unpack2(accr[q]);
        g_xl[(nb + 2 * q + 0) * 256 + tid] = vl.x + bvl;
        g_xl[(nb + 2 * q + 1) * 256 + tid] = vl.y + bvl;
        g_xr[(nb + 2 * q + 0) * 256 + tid] = vr.x + bvr;
        g_xr[(nb + 2 * q + 1) * 256 + tid] = vr.y + bvr;
    }
}

// ---------------- K2: count degrees + hash-insert physical keys ----------------
__global__ void count_insert_kernel(const int* __restrict__ dst, const int* __restrict__ pe) {
    int e = blockIdx.x * blockDim.x + threadIdx.x;
    if (e < EE) atomicAdd(&g_cnt[dst[e]], 1);
    if (e < 2 * PP) {
        int p = e >> 1;
        int i = pe[p * 2 + 0];
        int j = pe[p * 2 + 1];
        int key = (e & 1) ? (j * NN + i) : (i * NN + j);
        unsigned slot = ht_hash(key) & HT_MASK;
        while (true) {
            int old = atomicCAS(&g_htk[slot], -1, key);
            if (old == -1 || old == key) break;
            slot = (slot + 1) & HT_MASK;
        }
    }
}

// ---------------- K3: prefix scan over degrees ----------------
__global__ void scan_kernel() {
    __shared__ int part[1024];
    int t = threadIdx.x;
    const int CHUNK = 10;
    int base = t * CHUNK;
    int loc[CHUNK];
    int s = 0;
    #pragma unroll
    for (int i = 0; i < CHUNK; i++) {
        int idx = base + i;
        int v = (idx < NN) ? g_cnt[idx] : 0;
        loc[i] = s;
        s += v;
    }
    part[t] = s;
    __syncthreads();
    for (int off = 1; off < 1024; off <<= 1) {
        int v = (t >= off) ? part[t - off] : 0;
        __syncthreads();
        part[t] += v;
        __syncthreads();
    }
    int pre = (t > 0) ? part[t - 1] : 0;
    #pragma unroll
    for (int i = 0; i < CHUNK; i++) {
        int idx = base + i;
        if (idx < NN) {
            g_rowstart[idx] = pre + loc[i];
            g_cursor[idx] = pre + loc[i];
        }
    }
    if (t == 1023) g_rowstart[NN] = part[1023];
}

// ---------------- K4: scatter into CSR + hash-scan for min edge index ----------------
__global__ void scatter_scan_kernel(const int* __restrict__ src, const int* __restrict__ dst) {
    int e = blockIdx.x * blockDim.x + threadIdx.x;
    if (e >= EE) return;
    int sN = src[e], dN = dst[e];
    int pos = atomicAdd(&g_cursor[dN], 1);
    g_es[pos] = make_int2(sN, e);
    int key = sN * NN + dN;
    unsigned slot = ht_hash(key) & HT_MASK;
    while (true) {
        int kk = g_htk[slot];
        if (kk == -1) return;
        if (kk == key) { atomicMin(&g_htv[slot], e); return; }
        slot = (slot + 1) & HT_MASK;
    }
}

// ---------------- GATv2 edge phase: warp per (node, 128-ch half), online softmax ----------------
__global__ __launch_bounds__(256) void gat_edge(
    const float* __restrict__ eattr, const float* __restrict__ We,
    const float* __restrict__ att, const float* __restrict__ bias) {
    int tid = threadIdx.x;
    int l = tid & 31;
    int w = tid >> 5;
    int node = blockIdx.x * 4 + (w >> 1);
    int half = w & 1;
    int ch0 = half * 128 + l * 4;

    float wv0[4], wv1[4], wv2[4], av[4], xrv[4];
    int head = half * 2 + (l >> 4);
    int hk = (l & 15) * 4;
    #pragma unroll
    for (int k = 0; k < 4; k++) {
        wv0[k] = We[0 * 256 + ch0 + k];
        wv1[k] = We[1 * 256 + ch0 + k];
        wv2[k] = We[2 * 256 + ch0 + k];
        av[k] = att[head * 64 + hk + k];
    }
    {
        float4 r = *reinterpret_cast<const float4*>(g_xr + node * 256 + ch0);
        xrv[0] = r.x; xrv[1] = r.y; xrv[2] = r.z; xrv[3] = r.w;
    }
    int s0 = g_rowstart[node];
    int en = g_rowstart[node + 1];

    float m = -1e30f, ssum = 0.f;
    ull acc0 = 0ULL, acc1 = 0ULL;

    // software-pipelined edge loop
    int2 es; float ea0 = 0.f, ea1 = 0.f, ea2 = 0.f; float4 xa = make_float4(0, 0, 0, 0);
    if (s0 < en) {
        es = g_es[s0];
        ea0 = __ldg(eattr + es.y * 3 + 0);
        ea1 = __ldg(eattr + es.y * 3 + 1);
        ea2 = __ldg(eattr + es.y * 3 + 2);
        xa = *reinterpret_cast<const float4*>(g_xl + es.x * 256 + ch0);
    }
    for (int sp = s0; sp < en; sp++) {
        float a0 = ea0, a1 = ea1, a2 = ea2;
        float4 xc = xa;
        if (sp + 1 < en) {
            es = g_es[sp + 1];
            ea0 = __ldg(eattr + es.y * 3 + 0);
            ea1 = __ldg(eattr + es.y * 3 + 1);
            ea2 = __ldg(eattr + es.y * 3 + 2);
            xa = *reinterpret_cast<const float4*>(g_xl + es.x * 256 + ch0);
        }
        float xv[4] = {xc.x, xc.y, xc.z, xc.w};
        float part = 0.f;
        #pragma unroll
        for (int k = 0; k < 4; k++) {
            float t = xv[k] + xrv[k];
            t = fmaf(a0, wv0[k], t);
            t = fmaf(a1, wv1[k], t);
            t = fmaf(a2, wv2[k], t);
            t = fmaxf(t, 0.2f * t);       // leaky_relu 0.2
            part = fmaf(t, av[k], part);
        }
        part += __shfl_xor_sync(0xffffffffu, part, 1);
        part += __shfl_xor_sync(0xffffffffu, part, 2);
        part += __shfl_xor_sync(0xffffffffu, part, 4);
        part += __shfl_xor_sync(0xffffffffu, part, 8);

        float mn = fmaxf(m, part);
        float sc = __expf(m - mn);
        float p = __expf(part - mn);
        ssum = fmaf(ssum, sc, p);
        ull sc2 = pack2(sc, sc);
        ull p2 = pack2(p, p);
        acc0 = fma2(acc0, sc2, mul2(p2, pack2(xv[0], xv[1])));
        acc1 = fma2(acc1, sc2, mul2(p2, pack2(xv[2], xv[3])));
        m = mn;
    }

    float inv = 1.f / (ssum + 1e-16f);
    float2 a01 = unpack2(acc0);
    float2 a23 = unpack2(acc1);
    float o[4];
    float vv[4] = {a01.x, a01.y, a23.x, a23.y};
    #pragma unroll
    for (int k = 0; k < 4; k++) {
        float v = vv[k] * inv + bias[ch0 + k];
        o[k] = (v > 0.f) ? v : expm1f(v);
    }
    *reinterpret_cast<float4*>(g_h + node * 256 + ch0) = make_float4(o[0], o[1], o[2], o[3]);
}

// ---------------- layer-2 dual GEMM: 32 rows per block, packed f32x2 ----------------
__global__ __launch_bounds__(256) void gemm2(
    const float* __restrict__ Wl, const float* __restrict__ bl,
    const float* __restrict__ Wr, const float* __restrict__ br) {
    __shared__ __align__(16) float xs[256 * 36];   // K=256 rows of 32(+4 pad)
    int tid = threadIdx.x;
    int nb = blockIdx.x * 32;
    for (int idx = tid; idx < 32 * 256; idx += 256) {
        int i = idx / 256, k = idx % 256;
        int row = nb + i;
        xs[k * 36 + i] = (row < NN) ? g_h[row * 256 + k] : 0.f;
    }
    __syncthreads();
    ull accl[16], accr[16];
    #pragma unroll
    for (int q = 0; q < 16; q++) { accl[q] = 0ULL; accr[q] = 0ULL; }
    for (int k = 0; k < 256; k++) {
        float wl = __ldg(Wl + k * 256 + tid);
        float wr = __ldg(Wr + k * 256 + tid);
        ull wl2 = pack2(wl, wl);
        ull wr2 = pack2(wr, wr);
        const ulonglong2* xv = reinterpret_cast<const ulonglong2*>(xs + k * 36);
        #pragma unroll
        for (int q2 = 0; q2 < 8; q2++) {
            ulonglong2 a = xv[q2];
            accl[q2 * 2 + 0] = fma2(a.x, wl2, accl[q2 * 2 + 0]);
            accl[q2 * 2 + 1] = fma2(a.y, wl2, accl[q2 * 2 + 1]);
            accr[q2 * 2 + 0] = fma2(a.x, wr2, accr[q2 * 2 + 0]);
            accr[q2 * 2 + 1] = fma2(a.y, wr2, accr[q2 * 2 + 1]);
        }
    }
    float bvl = bl[tid], bvr = br[tid];
    #pragma unroll
    for (int q = 0; q < 16; q++) {
        int r0 = nb + 2 * q, r1 = nb + 2 * q + 1;
        float2 vl = unpack2(accl[q]);
        float2 vr = unpack2(accr[q]);
        if (r0 < NN) { g_xl[r0 * 256 + tid] = vl.x + bvl; g_xr[r0 * 256 + tid] = vr.x + bvr; }
        if (r1 < NN) { g_xl[r1 * 256 + tid] = vl.y + bvl; g_xr[r1 * 256 + tid] = vr.y + bvr; }
    }
}

// ---------------- merged heads kernel: blocks [0,500) edge head, [500,1125) node head ----------------
#define EDGE_BLOCKS (PP / 8)     // 500
__global__ __launch_bounds__(256) void heads_kernel(
    const int* __restrict__ pe, const float* __restrict__ eattr,
    const float* __restrict__ Wq1, const float* __restrict__ bq1,
    const float* __restrict__ Wq2, const float* __restrict__ bq2,
    const float* __restrict__ Wq3, const float* __restrict__ bq3,
    const float* __restrict__ Wn1, const float* __restrict__ bn1,
    const float* __restrict__ Wn2, const float* __restrict__ bn2,
    const float* __restrict__ Wn3, const float* __restrict__ bn3,
    float* __restrict__ out) {
    __shared__ float pool[5648];
    __shared__ int sidx[8];
    int tid = threadIdx.x;

    if (blockIdx.x < EDGE_BLOCKS) {
        // ---- edge-quality head: 515 -> 64 -> 32 -> 1 ----
        float* efs = pool;            // 8 x 520
        float* eq1 = pool + 4160;     // 8 x 64
        float* eq2 = pool + 4672;     // 8 x 33
        int pb = blockIdx.x * 8;
        if (tid < 8) {
            int p = pb + tid;
            int i = pe[p * 2 + 0];
            int j = pe[p * 2 + 1];
            sidx[tid] = min(ht_find(i * NN + j), ht_find(j * NN + i));
        }
        __syncthreads();
        for (int e8 = 0; e8 < 8; e8++) {
            int p = pb + e8;
            int i = pe[p * 2 + 0];
            int j = pe[p * 2 + 1];
            int idx = sidx[e8];
            for (int t = tid; t < 515; t += 256) {
                float v;
                if (t < 256) v = g_h[i * 256 + t];
                else if (t < 512) v = g_h[j * 256 + (t - 256)];
                else v = (idx < NOTF) ? eattr[idx * 3 + (t - 512)] : 0.f;
                efs[e8 * 520 + t] = v;
            }
        }
        __syncthreads();
        {
            int oc = tid & 63;
            int grp = tid >> 6;
            ull a01 = 0ULL;
            const float* ef0 = efs + (grp * 2 + 0) * 520;
            const float* ef1 = efs + (grp * 2 + 1) * 520;
            for (int k = 0; k < 515; k++) {
                float w = __ldg(Wq1 + k * 64 + oc);
                a01 = fma2(pack2(ef0[k], ef1[k]), pack2(w, w), a01);
            }
            float bb = bq1[oc];
            float2 a = unpack2(a01);
            float a0 = a.x + bb, a1 = a.y + bb;
            a0 = (a0 > 0.f) ? a0 : expm1f(a0);
            a1 = (a1 > 0.f) ? a1 : expm1f(a1);
            eq1[(grp * 2 + 0) * 64 + oc] = a0;
            eq1[(grp * 2 + 1) * 64 + oc] = a1;
        }
        __syncthreads();
        {
            int oc2 = tid & 31;
            int e8 = tid >> 5;
            float a = 0.f;
            for (int k = 0; k < 64; k++) a = fmaf(eq1[e8 * 64 + k], Wq2[k * 32 + oc2], a);
            a += bq2[oc2];
            a = (a > 0.f) ? a : expm1f(a);
            eq2[e8 * 33 + oc2] = a;
        }
        __syncthreads();
        {
            int w8 = tid >> 5;
            int lane = tid & 31;
            float v = eq2[w8 * 33 + lane] * Wq3[lane];
            v += __shfl_xor_sync(0xffffffffu, v, 16);
            v += __shfl_xor_sync(0xffffffffu, v, 8);
            v += __shfl_xor_sync(0xffffffffu, v, 4);
            v += __shfl_xor_sync(0xffffffffu, v, 2);
            v += __shfl_xor_sync(0xffffffffu, v, 1);
            if (lane == 0) out[pb + w8] = v + bq3[0];
        }
    } else {
        // ---- node swap head: 256 -> 64 -> 32 -> 1 ----
        float* hs = pool;             // 16 x 256
        float* eq1 = pool + 4096;     // 16 x 64
        float* eq2 = pool + 5120;     // 16 x 33
        int nb = (blockIdx.x - EDGE_BLOCKS) * 16;
        for (int t = tid; t < 16 * 256; t += 256) {
            int i = t >> 8;
            int c = t & 255;
            hs[i * 256 + c] = g_h[(nb + i) * 256 + c];
        }
        __syncthreads();
        {
            int oc = tid & 63;
            int grp = tid >> 6;
            ull acc01 = 0ULL, acc23 = 0ULL;
            for (int k = 0; k < 256; k++) {
                float w = __ldg(Wn1 + k * 64 + oc);
                ull w2 = pack2(w, w);
                acc01 = fma2(pack2(hs[(grp * 4 + 0) * 256 + k], hs[(grp * 4 + 1) * 256 + k]), w2, acc01);
                acc23 = fma2(pack2(hs[(grp * 4 + 2) * 256 + k], hs[(grp * 4 + 3) * 256 + k]), w2, acc23);
            }
            float bb = bn1[oc];
            float2 a01 = unpack2(acc01);
            float2 a23 = unpack2(acc23);
            float v[4] = {a01.x + bb, a01.y + bb, a23.x + bb, a23.y + bb};
            #pragma unroll
            for (int q = 0; q < 4; q++) {
                float a = v[q];
                a = (a > 0.f) ? a : expm1f(a);
                eq1[(grp * 4 + q) * 64 + oc] = a;
            }
        }
        __syncthreads();
        {
            int oc2 = tid & 31;
            int g2 = tid >> 5;
            ull b01 = 0ULL;
            for (int k = 0; k < 64; k++) {
                float w = Wn2[k * 32 + oc2];
                b01 = fma2(pack2(eq1[(g2 * 2 + 0) * 64 + k], eq1[(g2 * 2 + 1) * 64 + k]), pack2(w, w), b01);
            }
            float bb2 = bn2[oc2];
            float2 b = unpack2(b01);
            float b0 = b.x + bb2, b1 = b.y + bb2;
            b0 = (b0 > 0.f) ? b0 : expm1f(b0);
            b1 = (b1 > 0.f) ? b1 : expm1f(b1);
            eq2[(g2 * 2 + 0) * 33 + oc2] = b0;
            eq2[(g2 * 2 + 1) * 33 + oc2] = b1;
        }
        __syncthreads();
        {
            int w8 = tid >> 5;
            int lane = tid & 31;
            #pragma unroll
            for (int q = 0; q < 2; q++) {
                int nl = w8 * 2 + q;
                float v = eq2[nl * 33 + lane] * Wn3[lane];
                v += __shfl_xor_sync(0xffffffffu, v, 16);
                v += __shfl_xor_sync(0xffffffffu, v, 8);
                v += __shfl_xor_sync(0xffffffffu, v, 4);
                v += __shfl_xor_sync(0xffffffffu, v, 2);
                v += __shfl_xor_sync(0xffffffffu, v, 1);
                if (lane == 0) out[PP + nb + nl] = v + bn3[0];
            }
        }
    }
}

// ---------------- launch ----------------
extern "C" void kernel_launch(void* const* d_in, const int* in_sizes, int n_in,
                              void* d_out, int out_size) {
    const float* x   = (const float*)d_in[0];
    const int*   ei  = (const int*)d_in[1];
    const float* ea  = (const float*)d_in[2];
    const int*   pe  = (const int*)d_in[3];
    const float* Wl1 = (const float*)d_in[4];
    const float* bl1 = (const float*)d_in[5];
    const float* Wr1 = (const float*)d_in[6];
    const float* br1 = (const float*)d_in[7];
    const float* We1 = (const float*)d_in[8];
    const float* att1= (const float*)d_in[9];
    const float* b1  = (const float*)d_in[10];
    const float* Wl2 = (const float*)d_in[11];
    const float* bl2 = (const float*)d_in[12];
    const float* Wr2 = (const float*)d_in[13];
    const float* br2 = (const float*)d_in[14];
    const float* We2 = (const float*)d_in[15];
    const float* att2= (const float*)d_in[16];
    const float* b2  = (const float*)d_in[17];
    const float* Wq1 = (const float*)d_in[18];
    const float* bq1 = (const float*)d_in[19];
    const float* Wq2 = (const float*)d_in[20];
    const float* bq2 = (const float*)d_in[21];
    const float* Wq3 = (const float*)d_in[22];
    const float* bq3 = (const float*)d_in[23];
    const float* Wn1 = (const float*)d_in[24];
    const float* bn1 = (const float*)d_in[25];
    const float* Wn2 = (const float*)d_in[26];
    const float* bn2 = (const float*)d_in[27];
    const float* Wn3 = (const float*)d_in[28];
    const float* bn3 = (const float*)d_in[29];
    float* out = (float*)d_out;

    const int* src = ei;
    const int* dst = ei + EE;

    // K1: hash/count init + layer-1 GEMM (independent block ranges)
    k_init_gemm1<<<64 + NN / 16, 256>>>(x, Wl1, bl1, Wr1, br1);
    // K2..K4: CSR by dst + physical-edge min-index hash
    count_insert_kernel<<<(EE + 255) / 256, 256>>>(dst, pe);
    scan_kernel<<<1, 1024>>>();
    scatter_scan_kernel<<<(EE + 255) / 256, 256>>>(src, dst);

    // layer 1 attention
    gat_edge<<<NN / 4, 256>>>(ea, We1, att1, b1);
    // layer 2
    gemm2<<<(NN + 31) / 32, 256>>>(Wl2, bl2, Wr2, br2);
    gat_edge<<<NN / 4, 256>>>(ea, We2, att2, b2);

    // fused heads (edge quality + node swap), hash lookup inlined
    heads_kernel<<<EDGE_BLOCKS + (NN + 15) / 16, 256>>>(
        pe, ea, Wq1, bq1, Wq2, bq2, Wq3, bq3,
        Wn1, bn1, Wn2, bn2, Wn3, bn3, out);
}